// round 3
// baseline (speedup 1.0000x reference)
#include <cuda_runtime.h>

// Problem constants
#define HOPS  3
#define VOCAB 50257
#define EMB   128
#define MEM   256   // memory slots (M)
#define BATCH 16    // batch (B)
#define SENT  64    // sentence length (S)

// Scratch: E[t][b][m][d] = sum_s C[t+1][ story[m][b][s] ][d]   (t = 0..2 -> tables C1..C3)
// 3 * 16 * 256 * 128 * 4B = 6.29 MB device-global scratch (no allocation).
__device__ __align__(16) float g_E[3][BATCH][MEM][EMB];

// ---------------------------------------------------------------------------
// Kernel A: gather-sum embeddings. One WARP per (t, b, m).
//   - 64 tokens of the sentence are preloaded into 2 regs per lane, broadcast
//     via __shfl_sync (no repeated smem/gmem token reads).
//   - Each lane owns a float4 slice of the 128-dim row -> LDG.128, each token
//     reads a contiguous 512B table row across the warp.
// ---------------------------------------------------------------------------
__global__ void __launch_bounds__(128) gather_kernel(const int* __restrict__ story,
                                                     const float* __restrict__ C) {
    const int warps_per_block = blockDim.x >> 5;
    const int gw   = blockIdx.x * warps_per_block + (threadIdx.x >> 5);
    const int lane = threadIdx.x & 31;

    // gw in [0, 3*BATCH*MEM)
    const int t   = gw / (BATCH * MEM);
    const int rem = gw % (BATCH * MEM);
    const int b   = rem / MEM;
    const int m   = rem % MEM;

    // story layout: (MEM, BATCH, SENT) row-major
    const int* toks = story + ((size_t)m * BATCH + b) * SENT;
    const int tok_lo = toks[lane];
    const int tok_hi = toks[lane + 32];

    // table C[t+1]
    const float4* __restrict__ tab =
        (const float4*)(C + (size_t)(t + 1) * VOCAB * EMB);

    float4 acc = make_float4(0.f, 0.f, 0.f, 0.f);

#pragma unroll
    for (int s = 0; s < 32; s++) {
        int tok = __shfl_sync(0xffffffffu, tok_lo, s);
        float4 v = __ldg(tab + (size_t)tok * (EMB / 4) + lane);
        acc.x += v.x; acc.y += v.y; acc.z += v.z; acc.w += v.w;
    }
#pragma unroll
    for (int s = 0; s < 32; s++) {
        int tok = __shfl_sync(0xffffffffu, tok_hi, s);
        float4 v = __ldg(tab + (size_t)tok * (EMB / 4) + lane);
        acc.x += v.x; acc.y += v.y; acc.z += v.z; acc.w += v.w;
    }

    ((float4*)g_E[t][b][m])[lane] = acc;
}

// ---------------------------------------------------------------------------
// Kernel B: the hop loop. One block per batch element b (u depends only on b).
// 256 threads. Hop 0 collapses to a mean (softmax of zero logits is uniform).
//   hop h (h=1,2): logits from E[h-1], softmax over MEM, weighted sum of E[h].
// ---------------------------------------------------------------------------
__global__ void __launch_bounds__(256) hops_kernel(float* __restrict__ out) {
    __shared__ float u[EMB];
    __shared__ float prob[MEM];
    __shared__ float part[256];
    __shared__ float redA[8];
    __shared__ float redB[8];

    const int b    = blockIdx.x;
    const int tid  = threadIdx.x;
    const int warp = tid >> 5;
    const int lane = tid & 31;
    const int d    = tid & 127;    // 0..127
    const int half = tid >> 7;     // 0 or 1

    // ---- hop 0: u = mean over m of E[0][b][m]  (exactly uniform softmax) ----
    {
        float acc = 0.f;
        const int m0 = half * (MEM / 2);
#pragma unroll 4
        for (int m = m0; m < m0 + MEM / 2; m++)
            acc += g_E[0][b][m][d];
        part[tid] = acc;
        __syncthreads();
        if (tid < EMB)
            u[tid] = (part[tid] + part[tid + 128]) * (1.0f / MEM);
        __syncthreads();
    }

    // ---- hops 1 and 2 ----
    for (int h = 1; h <= 2; h++) {
        // logits[m] = dot(E[h-1][b][m], u); one warp handles 32 m's
        const float* __restrict__ Eh = &g_E[h - 1][b][0][0];
        float4 uv = ((const float4*)u)[lane];
        for (int mm = warp * 32; mm < warp * 32 + 32; mm++) {
            float4 e = __ldg(((const float4*)(Eh + (size_t)mm * EMB)) + lane);
            float dd = e.x * uv.x + e.y * uv.y + e.z * uv.z + e.w * uv.w;
#pragma unroll
            for (int off = 16; off; off >>= 1)
                dd += __shfl_xor_sync(0xffffffffu, dd, off);
            if (lane == 0) prob[mm] = dd;
        }
        __syncthreads();

        // softmax over prob[0..255]; one thread per m
        float x = prob[tid];
        float mx = x;
#pragma unroll
        for (int off = 16; off; off >>= 1)
            mx = fmaxf(mx, __shfl_xor_sync(0xffffffffu, mx, off));
        if (lane == 0) redA[warp] = mx;
        __syncthreads();
        mx = redA[0];
#pragma unroll
        for (int i = 1; i < 8; i++) mx = fmaxf(mx, redA[i]);

        float e = expf(x - mx);
        float sm = e;
#pragma unroll
        for (int off = 16; off; off >>= 1)
            sm += __shfl_xor_sync(0xffffffffu, sm, off);
        if (lane == 0) redB[warp] = sm;
        __syncthreads();
        sm = redB[0];
#pragma unroll
        for (int i = 1; i < 8; i++) sm += redB[i];

        prob[tid] = e / sm;
        __syncthreads();

        // o[d] = sum_m prob[m] * E[h][b][m][d];  u += o
        {
            const float* __restrict__ Ec = &g_E[h][b][0][0];
            float acc = 0.f;
            const int m0 = half * (MEM / 2);
#pragma unroll 4
            for (int m = m0; m < m0 + MEM / 2; m++)
                acc += prob[m] * Ec[(size_t)m * EMB + d];
            part[tid] = acc;
            __syncthreads();
            if (tid < EMB)
                u[tid] += part[tid] + part[tid + 128];
            __syncthreads();
        }
    }

    // write out[b][d]
    if (tid < EMB)
        out[(size_t)b * EMB + tid] = u[tid];
}

extern "C" void kernel_launch(void* const* d_in, const int* in_sizes, int n_in,
                              void* d_out, int out_size) {
    const int*   story = (const int*)d_in[0];   // (256, 16, 64) int32
    const float* C     = (const float*)d_in[1]; // (4, 50257, 128) fp32
    float*       out   = (float*)d_out;         // (16, 128) fp32

    (void)in_sizes; (void)n_in; (void)out_size;

    // 3 tables * BATCH * MEM warps, 4 warps per block
    const int total_warps = 3 * BATCH * MEM;          // 12288
    const int blocks = total_warps / 4;               // 3072
    gather_kernel<<<blocks, 128>>>(story, C);

    hops_kernel<<<BATCH, 256>>>(out);
}

// round 4
// speedup vs baseline: 1.4333x; 1.4333x over previous
#include <cuda_runtime.h>

// Problem constants
#define HOPS  3
#define VOCAB 50257
#define EMB   128
#define MEM   256   // memory slots (M)
#define BATCH 16    // batch (B)
#define SENT  64    // sentence length (S)

// Scratch: E[t][b][m][d] = sum_s C[t+1][ story[m][b][s] ][d]   (t = 0..2 -> tables C1..C3)
// 3 * 16 * 256 * 128 * 4B = 6.29 MB device-global scratch (no allocation).
__device__ __align__(16) float g_E[3][BATCH][MEM][EMB];

// ---------------------------------------------------------------------------
// Kernel A: gather-sum embeddings. One WARP per (t, b, m).
// Bound by L2 (LTS) traffic: 3 * 256*16*64 rows * 512B = ~402 MB. Near cap.
// ---------------------------------------------------------------------------
__global__ void __launch_bounds__(128) gather_kernel(const int* __restrict__ story,
                                                     const float* __restrict__ C) {
    const int warps_per_block = blockDim.x >> 5;
    const int gw   = blockIdx.x * warps_per_block + (threadIdx.x >> 5);
    const int lane = threadIdx.x & 31;

    const int t   = gw / (BATCH * MEM);
    const int rem = gw % (BATCH * MEM);
    const int b   = rem / MEM;
    const int m   = rem % MEM;

    // story layout: (MEM, BATCH, SENT) row-major
    const int* toks = story + ((size_t)m * BATCH + b) * SENT;
    const int tok_lo = toks[lane];
    const int tok_hi = toks[lane + 32];

    const float4* __restrict__ tab =
        (const float4*)(C + (size_t)(t + 1) * VOCAB * EMB);

    // two accumulators to shorten the FADD dependency chain
    float4 a0 = make_float4(0.f, 0.f, 0.f, 0.f);
    float4 a1 = make_float4(0.f, 0.f, 0.f, 0.f);

#pragma unroll
    for (int s = 0; s < 32; s++) {
        int tok = __shfl_sync(0xffffffffu, tok_lo, s);
        float4 v = __ldg(tab + (size_t)tok * (EMB / 4) + lane);
        a0.x += v.x; a0.y += v.y; a0.z += v.z; a0.w += v.w;
    }
#pragma unroll
    for (int s = 0; s < 32; s++) {
        int tok = __shfl_sync(0xffffffffu, tok_hi, s);
        float4 v = __ldg(tab + (size_t)tok * (EMB / 4) + lane);
        a1.x += v.x; a1.y += v.y; a1.z += v.z; a1.w += v.w;
    }

    float4 acc = make_float4(a0.x + a1.x, a0.y + a1.y, a0.z + a1.z, a0.w + a1.w);
    ((float4*)g_E[t][b][m])[lane] = acc;
}

// ---------------------------------------------------------------------------
// Kernel B: hop loop. One block of 1024 threads per batch element.
// All phases use 8 independent loads/thread (high MLP) + shallow reductions.
// ---------------------------------------------------------------------------
__global__ void __launch_bounds__(1024) hops_kernel(float* __restrict__ out) {
    __shared__ float4 part[32][32];   // per-warp partial float4s (16 KB)
    __shared__ float  prob[MEM];
    __shared__ float4 us[32];         // the state u, as 32 float4s
    __shared__ float  red[8];

    const int b    = blockIdx.x;
    const int tid  = threadIdx.x;
    const int w    = tid >> 5;        // warp 0..31
    const int lane = tid & 31;

    // ---------- hop 0: u = mean_m E0[b][m]  (softmax of zero logits = uniform) ----------
    {
        const float4* __restrict__ E0 = (const float4*)g_E[0][b];
        float4 acc = make_float4(0.f, 0.f, 0.f, 0.f);
#pragma unroll
        for (int k = 0; k < 8; k++) {
            float4 v = E0[(size_t)(w * 8 + k) * 32 + lane];
            acc.x += v.x; acc.y += v.y; acc.z += v.z; acc.w += v.w;
        }
        part[w][lane] = acc;
        __syncthreads();
#pragma unroll
        for (int off = 16; off >= 1; off >>= 1) {
            if (w < off) {
                float4 a = part[w][lane], c = part[w + off][lane];
                a.x += c.x; a.y += c.y; a.z += c.z; a.w += c.w;
                part[w][lane] = a;
            }
            __syncthreads();
        }
        if (tid < 32) {
            float4 a = part[0][tid];
            a.x *= (1.f / MEM); a.y *= (1.f / MEM); a.z *= (1.f / MEM); a.w *= (1.f / MEM);
            us[tid] = a;
        }
        __syncthreads();
    }

    // ---------- hops 1 and 2 ----------
    for (int h = 1; h <= 2; h++) {
        // --- logits[m] = dot(E[h-1][b][m], u). 4 lanes per slot, 8 loads each. ---
        {
            const float4* __restrict__ Ep = (const float4*)g_E[h - 1][b];
            const int q = lane & 3;           // quarter of the row (32 d's)
            const int m = w * 8 + (lane >> 2);
            float pd = 0.f;
#pragma unroll
            for (int j = 0; j < 8; j++) {
                float4 e  = Ep[(size_t)m * 32 + q + j * 4];
                float4 uu = us[q + j * 4];
                pd += e.x * uu.x + e.y * uu.y + e.z * uu.z + e.w * uu.w;
            }
            pd += __shfl_xor_sync(0xffffffffu, pd, 1);
            pd += __shfl_xor_sync(0xffffffffu, pd, 2);
            if (q == 0) prob[m] = pd;
            __syncthreads();
        }

        // --- softmax over prob[0..255] (warps 0..7 carry data) ---
        {
            float x = (tid < MEM) ? prob[tid] : -1e30f;
            float mx = x;
#pragma unroll
            for (int off = 16; off; off >>= 1)
                mx = fmaxf(mx, __shfl_xor_sync(0xffffffffu, mx, off));
            if (lane == 0 && w < 8) red[w] = mx;
            __syncthreads();
            mx = red[0];
#pragma unroll
            for (int i = 1; i < 8; i++) mx = fmaxf(mx, red[i]);
            __syncthreads();            // everyone done reading red before rewrite

            float ev = (tid < MEM) ? __expf(x - mx) : 0.f;
            float sv = ev;
#pragma unroll
            for (int off = 16; off; off >>= 1)
                sv += __shfl_xor_sync(0xffffffffu, sv, off);
            if (lane == 0 && w < 8) red[w] = sv;
            __syncthreads();
            float tot = red[0];
#pragma unroll
            for (int i = 1; i < 8; i++) tot += red[i];

            if (tid < MEM) prob[tid] = ev / tot;
            __syncthreads();
        }

        // --- o[d] = sum_m prob[m] * E[h][b][m][d]; u += o ---
        {
            const float4* __restrict__ Ec = (const float4*)g_E[h][b];
            float4 acc = make_float4(0.f, 0.f, 0.f, 0.f);
#pragma unroll
            for (int k = 0; k < 8; k++) {
                const int mm = w * 8 + k;
                float p = prob[mm];
                float4 v = Ec[(size_t)mm * 32 + lane];
                acc.x += p * v.x; acc.y += p * v.y; acc.z += p * v.z; acc.w += p * v.w;
            }
            part[w][lane] = acc;
            __syncthreads();
#pragma unroll
            for (int off = 16; off >= 1; off >>= 1) {
                if (w < off) {
                    float4 a = part[w][lane], c = part[w + off][lane];
                    a.x += c.x; a.y += c.y; a.z += c.z; a.w += c.w;
                    part[w][lane] = a;
                }
                __syncthreads();
            }
            if (tid < 32) {
                float4 a = us[tid], c = part[0][tid];
                a.x += c.x; a.y += c.y; a.z += c.z; a.w += c.w;
                us[tid] = a;
            }
            __syncthreads();
        }
    }

    // write out[b] (128 floats = 32 float4)
    if (tid < 32)
        ((float4*)out)[(size_t)b * 32 + tid] = us[tid];
}

extern "C" void kernel_launch(void* const* d_in, const int* in_sizes, int n_in,
                              void* d_out, int out_size) {
    const int*   story = (const int*)d_in[0];   // (256, 16, 64) int32
    const float* C     = (const float*)d_in[1]; // (4, 50257, 128) fp32
    float*       out   = (float*)d_out;         // (16, 128) fp32

    (void)in_sizes; (void)n_in; (void)out_size;

    const int total_warps = 3 * BATCH * MEM;          // 12288
    const int blocks = total_warps / 4;               // 3072
    gather_kernel<<<blocks, 128>>>(story, C);

    hops_kernel<<<BATCH, 1024>>>(out);
}